// round 1
// baseline (speedup 1.0000x reference)
#include <cuda_runtime.h>
#include <math.h>
#include <float.h>

#define T_SEQ 2048
#define NH 16
#define HD 128
#define DIM 2048
#define QKV_DIM 6144
#define BQ 64
#define BKEY 64
#define KT_STRIDE 68
#define ATTN_SMEM ((BQ*HD + HD*KT_STRIDE + BKEY*HD + BQ*BKEY + 3*BQ) * 4)

// scratch (allocation-free rule: static device globals)
__device__ float g_qkv[2L * T_SEQ * QKV_DIM];   // [B,T,6144]
__device__ float g_att[2L * T_SEQ * DIM];       // [B,T,2048] attention output

// ---------------------------------------------------------------------------
// SGEMM: C[M,N] = A[M,K] * B[N,K]^T   (both operands row-major, K-contiguous)
// 128x128 block tile, BK=16, 256 threads, 8x8 per thread, float4 everywhere.
// ---------------------------------------------------------------------------
__global__ __launch_bounds__(256) void sgemm_nt(const float* __restrict__ A,
                                                const float* __restrict__ B,
                                                float* __restrict__ C,
                                                int M, int N, int K) {
    __shared__ float As[16][128];
    __shared__ float Bs[16][128];
    int tid = threadIdx.x;
    const float* Ab = A + (size_t)blockIdx.y * 128 * K;
    const float* Bb = B + (size_t)blockIdx.x * 128 * K;

    float acc[8][8];
#pragma unroll
    for (int i = 0; i < 8; i++)
#pragma unroll
        for (int j = 0; j < 8; j++) acc[i][j] = 0.f;

    int tr = tid >> 4;          // 0..15 (row group)
    int tc = tid & 15;          // 0..15 (col group)
    int lr = tid >> 2;          // 0..63 (load row)
    int lc = (tid & 3) << 2;    // 0,4,8,12 (load col base)

    for (int k0 = 0; k0 < K; k0 += 16) {
#pragma unroll
        for (int rr = 0; rr < 2; ++rr) {
            int row = lr + rr * 64;
            float4 a4 = *(const float4*)(Ab + (size_t)row * K + k0 + lc);
            As[lc + 0][row] = a4.x; As[lc + 1][row] = a4.y;
            As[lc + 2][row] = a4.z; As[lc + 3][row] = a4.w;
            float4 b4 = *(const float4*)(Bb + (size_t)row * K + k0 + lc);
            Bs[lc + 0][row] = b4.x; Bs[lc + 1][row] = b4.y;
            Bs[lc + 2][row] = b4.z; Bs[lc + 3][row] = b4.w;
        }
        __syncthreads();
#pragma unroll
        for (int kk = 0; kk < 16; ++kk) {
            float a[8], b[8];
            *(float4*)&a[0] = *(const float4*)&As[kk][tr * 8];
            *(float4*)&a[4] = *(const float4*)&As[kk][tr * 8 + 4];
            *(float4*)&b[0] = *(const float4*)&Bs[kk][tc * 8];
            *(float4*)&b[4] = *(const float4*)&Bs[kk][tc * 8 + 4];
#pragma unroll
            for (int i = 0; i < 8; i++)
#pragma unroll
                for (int j = 0; j < 8; j++)
                    acc[i][j] = fmaf(a[i], b[j], acc[i][j]);
        }
        __syncthreads();
    }

    float* Cb = C + (size_t)(blockIdx.y * 128 + tr * 8) * N + blockIdx.x * 128 + tc * 8;
#pragma unroll
    for (int i = 0; i < 8; i++) {
        *(float4*)(Cb + (size_t)i * N)     = make_float4(acc[i][0], acc[i][1], acc[i][2], acc[i][3]);
        *(float4*)(Cb + (size_t)i * N + 4) = make_float4(acc[i][4], acc[i][5], acc[i][6], acc[i][7]);
    }
}

// ---------------------------------------------------------------------------
// RoPE in-place on q and k halves of g_qkv.
// One thread per (b,t,h,p) with p in [0,64): rotates (p, p+64) pair.
// ---------------------------------------------------------------------------
__global__ __launch_bounds__(256) void rope_kernel() {
    int idx = blockIdx.x * 256 + threadIdx.x;   // < 2*2048*16*64 = 4194304
    int p = idx & 63;
    int h = (idx >> 6) & 15;
    int t = (idx >> 10) & 2047;
    int b = idx >> 21;

    float inv_freq = powf(10000.0f, -(float)p * (1.0f / 64.0f));
    float ang = (float)t * inv_freq;
    float s, c;
    sincosf(ang, &s, &c);

    size_t base = ((size_t)(b * T_SEQ + t)) * QKV_DIM + h * HD + p;
    float q1 = g_qkv[base], q2 = g_qkv[base + 64];
    g_qkv[base]      = q1 * c - q2 * s;
    g_qkv[base + 64] = q1 * s + q2 * c;
    float k1 = g_qkv[base + DIM], k2 = g_qkv[base + DIM + 64];
    g_qkv[base + DIM]      = k1 * c - k2 * s;
    g_qkv[base + DIM + 64] = k1 * s + k2 * c;
}

// ---------------------------------------------------------------------------
// Causal flash attention, fp32. One block per (q-tile of 64, head, batch).
// 256 threads = 16x16: each thread owns 4 query rows x (4 score cols / 8 out cols).
// Online softmax with running (m, l) in smem.
// ---------------------------------------------------------------------------
__global__ __launch_bounds__(256) void attn_kernel() {
    extern __shared__ float sm[];
    float* q_s  = sm;                       // [64][128]
    float* kT_s = q_s + BQ * HD;            // [128][68]  (K transposed, padded)
    float* v_s  = kT_s + HD * KT_STRIDE;    // [64][128]
    float* s_s  = v_s + BKEY * HD;          // [64][64]
    float* m_s  = s_s + BQ * BKEY;          // [64]
    float* l_s  = m_s + BQ;                 // [64]
    float* a_s  = l_s + BQ;                 // [64]

    int qt = blockIdx.x, h = blockIdx.y, b = blockIdx.z;
    int tid = threadIdx.x;
    int ty = tid >> 4, tx = tid & 15;
    int warp = tid >> 5, lane = tid & 31;

    const float* qbase = g_qkv + ((size_t)b * T_SEQ) * QKV_DIM + h * HD;
    const float* kbase = qbase + DIM;
    const float* vbase = qbase + 2 * DIM;
    int q0 = qt * BQ;

    // load Q tile [64][128]
    for (int i = tid; i < BQ * (HD / 4); i += 256) {
        int r = i >> 5, c4 = (i & 31) * 4;
        *(float4*)&q_s[r * HD + c4] =
            *(const float4*)(qbase + (size_t)(q0 + r) * QKV_DIM + c4);
    }
    if (tid < BQ) { m_s[tid] = -1e30f; l_s[tid] = 0.f; }

    float o[4][8];
#pragma unroll
    for (int i = 0; i < 4; i++)
#pragma unroll
        for (int j = 0; j < 8; j++) o[i][j] = 0.f;

    const float scale = 0.08838834764831845f;  // 1/sqrt(128)

    for (int kt = 0; kt <= qt; ++kt) {
        int k0 = kt * BKEY;
        __syncthreads();  // protect kT_s/v_s/s_s from previous iteration readers

        // load K tile transposed: kT_s[d][key]
        for (int i = tid; i < BKEY * (HD / 4); i += 256) {
            int r = i >> 5, c4 = (i & 31) * 4;
            float4 kv = *(const float4*)(kbase + (size_t)(k0 + r) * QKV_DIM + c4);
            kT_s[(c4 + 0) * KT_STRIDE + r] = kv.x;
            kT_s[(c4 + 1) * KT_STRIDE + r] = kv.y;
            kT_s[(c4 + 2) * KT_STRIDE + r] = kv.z;
            kT_s[(c4 + 3) * KT_STRIDE + r] = kv.w;
        }
        // load V tile [key][d]
        for (int i = tid; i < BKEY * (HD / 4); i += 256) {
            int r = i >> 5, c4 = (i & 31) * 4;
            *(float4*)&v_s[r * HD + c4] =
                *(const float4*)(vbase + (size_t)(k0 + r) * QKV_DIM + c4);
        }
        __syncthreads();

        // S = Q K^T : thread computes 4x4 (rows ty*4.., cols tx*4..)
        float s[4][4];
#pragma unroll
        for (int i = 0; i < 4; i++)
#pragma unroll
            for (int j = 0; j < 4; j++) s[i][j] = 0.f;

        for (int d4 = 0; d4 < HD / 4; ++d4) {
            float4 qf[4];
#pragma unroll
            for (int i = 0; i < 4; i++)
                qf[i] = *(const float4*)&q_s[(ty * 4 + i) * HD + d4 * 4];
#pragma unroll
            for (int dd = 0; dd < 4; ++dd) {
                float4 kf = *(const float4*)&kT_s[(d4 * 4 + dd) * KT_STRIDE + tx * 4];
#pragma unroll
                for (int i = 0; i < 4; i++) {
                    float qv = ((const float*)&qf[i])[dd];
                    s[i][0] = fmaf(qv, kf.x, s[i][0]);
                    s[i][1] = fmaf(qv, kf.y, s[i][1]);
                    s[i][2] = fmaf(qv, kf.z, s[i][2]);
                    s[i][3] = fmaf(qv, kf.w, s[i][3]);
                }
            }
        }

        // scale + causal mask + store to smem
#pragma unroll
        for (int i = 0; i < 4; i++) {
            int qi = q0 + ty * 4 + i;
            float4 sv;
            float* sp = (float*)&sv;
#pragma unroll
            for (int j = 0; j < 4; j++) {
                int kj = k0 + tx * 4 + j;
                float val = s[i][j] * scale;
                sp[j] = (kj > qi) ? -1e30f : val;
            }
            *(float4*)&s_s[(ty * 4 + i) * BKEY + tx * 4] = sv;
        }
        __syncthreads();

        // online softmax: each warp owns 8 rows
        for (int rr = 0; rr < 8; ++rr) {
            int r = warp * 8 + rr;
            float x0 = s_s[r * BKEY + lane];
            float x1 = s_s[r * BKEY + 32 + lane];
            float mx = fmaxf(x0, x1);
#pragma unroll
            for (int off = 16; off > 0; off >>= 1)
                mx = fmaxf(mx, __shfl_xor_sync(0xffffffffu, mx, off));
            float mold = m_s[r];
            float mnew = fmaxf(mold, mx);
            float p0 = __expf(x0 - mnew);
            float p1 = __expf(x1 - mnew);
            s_s[r * BKEY + lane] = p0;
            s_s[r * BKEY + 32 + lane] = p1;
            float sum = p0 + p1;
#pragma unroll
            for (int off = 16; off > 0; off >>= 1)
                sum += __shfl_xor_sync(0xffffffffu, sum, off);
            if (lane == 0) {
                float alpha = __expf(mold - mnew);
                a_s[r] = alpha;
                m_s[r] = mnew;
                l_s[r] = l_s[r] * alpha + sum;
            }
        }
        __syncthreads();

        // rescale O and accumulate P V
        float al[4];
#pragma unroll
        for (int i = 0; i < 4; i++) al[i] = a_s[ty * 4 + i];
#pragma unroll
        for (int i = 0; i < 4; i++)
#pragma unroll
            for (int j = 0; j < 8; j++) o[i][j] *= al[i];

#pragma unroll 4
        for (int k = 0; k < BKEY; ++k) {
            float p0v = s_s[(ty * 4 + 0) * BKEY + k];
            float p1v = s_s[(ty * 4 + 1) * BKEY + k];
            float p2v = s_s[(ty * 4 + 2) * BKEY + k];
            float p3v = s_s[(ty * 4 + 3) * BKEY + k];
            float4 va = *(const float4*)&v_s[k * HD + tx * 8];
            float4 vb = *(const float4*)&v_s[k * HD + tx * 8 + 4];
            float vv[8] = {va.x, va.y, va.z, va.w, vb.x, vb.y, vb.z, vb.w};
#pragma unroll
            for (int j = 0; j < 8; j++) {
                o[0][j] = fmaf(p0v, vv[j], o[0][j]);
                o[1][j] = fmaf(p1v, vv[j], o[1][j]);
                o[2][j] = fmaf(p2v, vv[j], o[2][j]);
                o[3][j] = fmaf(p3v, vv[j], o[3][j]);
            }
        }
    }

    // finalize: divide by l, write [B,T,H*D]
#pragma unroll
    for (int i = 0; i < 4; i++) {
        float inv = 1.0f / l_s[ty * 4 + i];
        size_t off = ((size_t)(b * T_SEQ + q0 + ty * 4 + i)) * DIM + h * HD + tx * 8;
        *(float4*)&g_att[off] =
            make_float4(o[i][0] * inv, o[i][1] * inv, o[i][2] * inv, o[i][3] * inv);
        *(float4*)&g_att[off + 4] =
            make_float4(o[i][4] * inv, o[i][5] * inv, o[i][6] * inv, o[i][7] * inv);
    }
}

// ---------------------------------------------------------------------------
extern "C" void kernel_launch(void* const* d_in, const int* in_sizes, int n_in,
                              void* d_out, int out_size) {
    const float* x     = (const float*)d_in[0];  // [2,2048,2048]
    const float* w_qkv = (const float*)d_in[1];  // [6144,2048]
    const float* w_out = (const float*)d_in[2];  // [2048,2048]
    float* out = (float*)d_out;                  // [2,2048,2048]

    float* qkv_ptr = nullptr;
    float* att_ptr = nullptr;
    cudaGetSymbolAddress((void**)&qkv_ptr, g_qkv);
    cudaGetSymbolAddress((void**)&att_ptr, g_att);
    cudaFuncSetAttribute(attn_kernel, cudaFuncAttributeMaxDynamicSharedMemorySize, ATTN_SMEM);

    // 1) QKV projection: [4096,2048] x [6144,2048]^T
    sgemm_nt<<<dim3(QKV_DIM / 128, 4096 / 128), 256>>>(x, w_qkv, qkv_ptr, 4096, QKV_DIM, DIM);
    // 2) RoPE on q,k
    rope_kernel<<<(2 * T_SEQ * NH * 64) / 256, 256>>>();
    // 3) causal attention
    attn_kernel<<<dim3(T_SEQ / BQ, NH, 2), 256, ATTN_SMEM>>>();
    // 4) output projection: [4096,2048] x [2048,2048]^T
    sgemm_nt<<<dim3(DIM / 128, 4096 / 128), 256>>>(att_ptr, w_out, out, 4096, DIM, DIM);
}

// round 2
// speedup vs baseline: 1.0376x; 1.0376x over previous
#include <cuda_runtime.h>
#include <math.h>
#include <float.h>

#define T_SEQ 2048
#define NH 16
#define HD 128
#define DIM 2048
#define QKV_DIM 6144
#define BQ 64
#define BKEY 64
#define KT_STRIDE 68
#define ATTN_SMEM ((BQ*HD + HD*KT_STRIDE + BKEY*HD + BQ*BKEY + 3*BQ) * 4)

typedef unsigned long long u64;

// ---- packed f32x2 primitives (FFMA2 path: 2x fp32 throughput on sm_103a) ----
__device__ __forceinline__ u64 ffma2(u64 a, u64 b, u64 c) {
    u64 d;
    asm("fma.rn.f32x2 %0, %1, %2, %3;" : "=l"(d) : "l"(a), "l"(b), "l"(c));
    return d;
}
__device__ __forceinline__ u64 fmul2(u64 a, u64 b) {
    u64 d;
    asm("mul.rn.f32x2 %0, %1, %2;" : "=l"(d) : "l"(a), "l"(b));
    return d;
}
__device__ __forceinline__ u64 pack2(float x, float y) {
    u64 r;
    asm("mov.b64 %0, {%1, %2};" : "=l"(r) : "f"(x), "f"(y));
    return r;
}
__device__ __forceinline__ float2 unpack2(u64 v) {
    float2 r;
    asm("mov.b64 {%0, %1}, %2;" : "=f"(r.x), "=f"(r.y) : "l"(v));
    return r;
}

// scratch (allocation-free rule: static device globals)
__device__ float g_qkv[2L * T_SEQ * QKV_DIM];   // [B,T,6144]
__device__ float g_att[2L * T_SEQ * DIM];       // [B,T,2048]

// ---------------------------------------------------------------------------
// SGEMM: C[M,N] = A[M,K] * B[N,K]^T  (row-major, K-contiguous), f32x2 inner.
// 128x128 tile, BK=16, 256 threads, 8x8/thread, global-load software pipeline.
// ---------------------------------------------------------------------------
__global__ __launch_bounds__(256) void sgemm_nt(const float* __restrict__ A,
                                                const float* __restrict__ B,
                                                float* __restrict__ C,
                                                int M, int N, int K) {
    __shared__ float As[16][128];
    __shared__ float Bs[16][128];
    int tid = threadIdx.x;
    const float* Ab = A + (size_t)blockIdx.y * 128 * K;
    const float* Bb = B + (size_t)blockIdx.x * 128 * K;

    u64 acc[8][4];
#pragma unroll
    for (int i = 0; i < 8; i++)
#pragma unroll
        for (int j = 0; j < 4; j++) acc[i][j] = 0ull;   // {0.f,0.f}

    int tr = tid >> 4;          // 0..15
    int tc = tid & 15;          // 0..15
    int lr = tid >> 2;          // 0..63
    int lc = (tid & 3) << 2;    // 0,4,8,12

    // prologue prefetch of k0 = 0
    float4 pa[2], pb[2];
#pragma unroll
    for (int rr = 0; rr < 2; ++rr) {
        int row = lr + rr * 64;
        pa[rr] = *(const float4*)(Ab + (size_t)row * K + lc);
        pb[rr] = *(const float4*)(Bb + (size_t)row * K + lc);
    }

    for (int k0 = 0; k0 < K; k0 += 16) {
#pragma unroll
        for (int rr = 0; rr < 2; ++rr) {
            int row = lr + rr * 64;
            As[lc + 0][row] = pa[rr].x; As[lc + 1][row] = pa[rr].y;
            As[lc + 2][row] = pa[rr].z; As[lc + 3][row] = pa[rr].w;
            Bs[lc + 0][row] = pb[rr].x; Bs[lc + 1][row] = pb[rr].y;
            Bs[lc + 2][row] = pb[rr].z; Bs[lc + 3][row] = pb[rr].w;
        }
        __syncthreads();

        // prefetch next K-slab while computing this one
        if (k0 + 16 < K) {
#pragma unroll
            for (int rr = 0; rr < 2; ++rr) {
                int row = lr + rr * 64;
                pa[rr] = *(const float4*)(Ab + (size_t)row * K + k0 + 16 + lc);
                pb[rr] = *(const float4*)(Bb + (size_t)row * K + k0 + 16 + lc);
            }
        }

#pragma unroll
        for (int kk = 0; kk < 16; ++kk) {
            float4 a0 = *(const float4*)&As[kk][tr * 8];
            float4 a1 = *(const float4*)&As[kk][tr * 8 + 4];
            float4 b0 = *(const float4*)&Bs[kk][tc * 8];
            float4 b1 = *(const float4*)&Bs[kk][tc * 8 + 4];
            u64 bb[4] = { pack2(b0.x, b0.y), pack2(b0.z, b0.w),
                          pack2(b1.x, b1.y), pack2(b1.z, b1.w) };
            float av[8] = {a0.x, a0.y, a0.z, a0.w, a1.x, a1.y, a1.z, a1.w};
#pragma unroll
            for (int i = 0; i < 8; i++) {
                u64 ap = pack2(av[i], av[i]);
#pragma unroll
                for (int j = 0; j < 4; j++)
                    acc[i][j] = ffma2(ap, bb[j], acc[i][j]);
            }
        }
        __syncthreads();
    }

    float* Cb = C + (size_t)(blockIdx.y * 128 + tr * 8) * N + blockIdx.x * 128 + tc * 8;
#pragma unroll
    for (int i = 0; i < 8; i++) {
        float2 c0 = unpack2(acc[i][0]), c1 = unpack2(acc[i][1]);
        float2 c2 = unpack2(acc[i][2]), c3 = unpack2(acc[i][3]);
        *(float4*)(Cb + (size_t)i * N)     = make_float4(c0.x, c0.y, c1.x, c1.y);
        *(float4*)(Cb + (size_t)i * N + 4) = make_float4(c2.x, c2.y, c3.x, c3.y);
    }
}

// ---------------------------------------------------------------------------
// RoPE in-place on q and k halves of g_qkv.
// ---------------------------------------------------------------------------
__global__ __launch_bounds__(256) void rope_kernel() {
    int idx = blockIdx.x * 256 + threadIdx.x;
    int p = idx & 63;
    int h = (idx >> 6) & 15;
    int t = (idx >> 10) & 2047;
    int b = idx >> 21;

    float inv_freq = powf(10000.0f, -(float)p * (1.0f / 64.0f));
    float ang = (float)t * inv_freq;
    float s, c;
    sincosf(ang, &s, &c);

    size_t base = ((size_t)(b * T_SEQ + t)) * QKV_DIM + h * HD + p;
    float q1 = g_qkv[base], q2 = g_qkv[base + 64];
    g_qkv[base]      = q1 * c - q2 * s;
    g_qkv[base + 64] = q1 * s + q2 * c;
    float k1 = g_qkv[base + DIM], k2 = g_qkv[base + DIM + 64];
    g_qkv[base + DIM]      = k1 * c - k2 * s;
    g_qkv[base + DIM + 64] = k1 * s + k2 * c;
}

// ---------------------------------------------------------------------------
// Causal flash attention, fp32, f32x2 inner loops.
// ---------------------------------------------------------------------------
__global__ __launch_bounds__(256) void attn_kernel() {
    extern __shared__ float sm[];
    float* q_s  = sm;                       // [64][128]
    float* kT_s = q_s + BQ * HD;            // [128][68]
    float* v_s  = kT_s + HD * KT_STRIDE;    // [64][128]
    float* s_s  = v_s + BKEY * HD;          // [64][64]
    float* m_s  = s_s + BQ * BKEY;          // [64]
    float* l_s  = m_s + BQ;                 // [64]
    float* a_s  = l_s + BQ;                 // [64]

    int qt = blockIdx.x, h = blockIdx.y, b = blockIdx.z;
    int tid = threadIdx.x;
    int ty = tid >> 4, tx = tid & 15;
    int warp = tid >> 5, lane = tid & 31;

    const float* qbase = g_qkv + ((size_t)b * T_SEQ) * QKV_DIM + h * HD;
    const float* kbase = qbase + DIM;
    const float* vbase = qbase + 2 * DIM;
    int q0 = qt * BQ;

    for (int i = tid; i < BQ * (HD / 4); i += 256) {
        int r = i >> 5, c4 = (i & 31) * 4;
        *(float4*)&q_s[r * HD + c4] =
            *(const float4*)(qbase + (size_t)(q0 + r) * QKV_DIM + c4);
    }
    if (tid < BQ) { m_s[tid] = -1e30f; l_s[tid] = 0.f; }

    u64 o2[4][4];
#pragma unroll
    for (int i = 0; i < 4; i++)
#pragma unroll
        for (int j = 0; j < 4; j++) o2[i][j] = 0ull;

    const float scale = 0.08838834764831845f;  // 1/sqrt(128)

    for (int kt = 0; kt <= qt; ++kt) {
        int k0 = kt * BKEY;
        __syncthreads();

        for (int i = tid; i < BKEY * (HD / 4); i += 256) {
            int r = i >> 5, c4 = (i & 31) * 4;
            float4 kv = *(const float4*)(kbase + (size_t)(k0 + r) * QKV_DIM + c4);
            kT_s[(c4 + 0) * KT_STRIDE + r] = kv.x;
            kT_s[(c4 + 1) * KT_STRIDE + r] = kv.y;
            kT_s[(c4 + 2) * KT_STRIDE + r] = kv.z;
            kT_s[(c4 + 3) * KT_STRIDE + r] = kv.w;
        }
        for (int i = tid; i < BKEY * (HD / 4); i += 256) {
            int r = i >> 5, c4 = (i & 31) * 4;
            *(float4*)&v_s[r * HD + c4] =
                *(const float4*)(vbase + (size_t)(k0 + r) * QKV_DIM + c4);
        }
        __syncthreads();

        // S = Q K^T : thread computes rows ty*4.., cols tx*4.. (packed pairs)
        u64 s2[4][2];
#pragma unroll
        for (int i = 0; i < 4; i++) { s2[i][0] = 0ull; s2[i][1] = 0ull; }

        for (int d4 = 0; d4 < HD / 4; ++d4) {
            float4 qf[4];
#pragma unroll
            for (int i = 0; i < 4; i++)
                qf[i] = *(const float4*)&q_s[(ty * 4 + i) * HD + d4 * 4];
#pragma unroll
            for (int dd = 0; dd < 4; ++dd) {
                float4 kf = *(const float4*)&kT_s[(d4 * 4 + dd) * KT_STRIDE + tx * 4];
                u64 k01 = pack2(kf.x, kf.y);
                u64 k23 = pack2(kf.z, kf.w);
#pragma unroll
                for (int i = 0; i < 4; i++) {
                    float qv = ((const float*)&qf[i])[dd];
                    u64 qp = pack2(qv, qv);
                    s2[i][0] = ffma2(qp, k01, s2[i][0]);
                    s2[i][1] = ffma2(qp, k23, s2[i][1]);
                }
            }
        }

        // scale + causal mask + store
#pragma unroll
        for (int i = 0; i < 4; i++) {
            int qi = q0 + ty * 4 + i;
            float2 sa = unpack2(s2[i][0]);
            float2 sb = unpack2(s2[i][1]);
            float sv[4] = {sa.x, sa.y, sb.x, sb.y};
            float4 outv;
            float* op = (float*)&outv;
#pragma unroll
            for (int j = 0; j < 4; j++) {
                int kj = k0 + tx * 4 + j;
                op[j] = (kj > qi) ? -1e30f : sv[j] * scale;
            }
            *(float4*)&s_s[(ty * 4 + i) * BKEY + tx * 4] = outv;
        }
        __syncthreads();

        // online softmax: each warp owns 8 rows
        for (int rr = 0; rr < 8; ++rr) {
            int r = warp * 8 + rr;
            float x0 = s_s[r * BKEY + lane];
            float x1 = s_s[r * BKEY + 32 + lane];
            float mx = fmaxf(x0, x1);
#pragma unroll
            for (int off = 16; off > 0; off >>= 1)
                mx = fmaxf(mx, __shfl_xor_sync(0xffffffffu, mx, off));
            float mold = m_s[r];
            float mnew = fmaxf(mold, mx);
            float p0 = __expf(x0 - mnew);
            float p1 = __expf(x1 - mnew);
            s_s[r * BKEY + lane] = p0;
            s_s[r * BKEY + 32 + lane] = p1;
            float sum = p0 + p1;
#pragma unroll
            for (int off = 16; off > 0; off >>= 1)
                sum += __shfl_xor_sync(0xffffffffu, sum, off);
            if (lane == 0) {
                float alpha = __expf(mold - mnew);
                a_s[r] = alpha;
                m_s[r] = mnew;
                l_s[r] = l_s[r] * alpha + sum;
            }
        }
        __syncthreads();

        // rescale O and accumulate P V (packed pairs along head-dim)
#pragma unroll
        for (int i = 0; i < 4; i++) {
            u64 alp = pack2(a_s[ty * 4 + i], a_s[ty * 4 + i]);
#pragma unroll
            for (int j = 0; j < 4; j++) o2[i][j] = fmul2(o2[i][j], alp);
        }

        for (int k = 0; k < BKEY; k += 4) {
            float4 p4[4];
#pragma unroll
            for (int i = 0; i < 4; i++)
                p4[i] = *(const float4*)&s_s[(ty * 4 + i) * BKEY + k];
#pragma unroll
            for (int kk = 0; kk < 4; ++kk) {
                float4 va = *(const float4*)&v_s[(k + kk) * HD + tx * 8];
                float4 vb = *(const float4*)&v_s[(k + kk) * HD + tx * 8 + 4];
                u64 vv[4] = { pack2(va.x, va.y), pack2(va.z, va.w),
                              pack2(vb.x, vb.y), pack2(vb.z, vb.w) };
#pragma unroll
                for (int i = 0; i < 4; i++) {
                    float pv = ((const float*)&p4[i])[kk];
                    u64 pp = pack2(pv, pv);
#pragma unroll
                    for (int j = 0; j < 4; j++)
                        o2[i][j] = ffma2(pp, vv[j], o2[i][j]);
                }
            }
        }
    }

    // finalize
#pragma unroll
    for (int i = 0; i < 4; i++) {
        float inv = 1.0f / l_s[ty * 4 + i];
        float2 oa = unpack2(o2[i][0]), ob = unpack2(o2[i][1]);
        float2 oc = unpack2(o2[i][2]), od = unpack2(o2[i][3]);
        size_t off = ((size_t)(b * T_SEQ + q0 + ty * 4 + i)) * DIM + h * HD + tx * 8;
        *(float4*)&g_att[off] =
            make_float4(oa.x * inv, oa.y * inv, ob.x * inv, ob.y * inv);
        *(float4*)&g_att[off + 4] =
            make_float4(oc.x * inv, oc.y * inv, od.x * inv, od.y * inv);
    }
}

// ---------------------------------------------------------------------------
extern "C" void kernel_launch(void* const* d_in, const int* in_sizes, int n_in,
                              void* d_out, int out_size) {
    const float* x     = (const float*)d_in[0];  // [2,2048,2048]
    const float* w_qkv = (const float*)d_in[1];  // [6144,2048]
    const float* w_out = (const float*)d_in[2];  // [2048,2048]
    float* out = (float*)d_out;                  // [2,2048,2048]

    float* qkv_ptr = nullptr;
    float* att_ptr = nullptr;
    cudaGetSymbolAddress((void**)&qkv_ptr, g_qkv);
    cudaGetSymbolAddress((void**)&att_ptr, g_att);
    cudaFuncSetAttribute(attn_kernel, cudaFuncAttributeMaxDynamicSharedMemorySize, ATTN_SMEM);

    // 1) QKV projection
    sgemm_nt<<<dim3(QKV_DIM / 128, 4096 / 128), 256>>>(x, w_qkv, qkv_ptr, 4096, QKV_DIM, DIM);
    // 2) RoPE
    rope_kernel<<<(2 * T_SEQ * NH * 64) / 256, 256>>>();
    // 3) causal attention
    attn_kernel<<<dim3(T_SEQ / BQ, NH, 2), 256, ATTN_SMEM>>>();
    // 4) output projection
    sgemm_nt<<<dim3(DIM / 128, 4096 / 128), 256>>>(att_ptr, w_out, out, 4096, DIM, DIM);
}

// round 4
// speedup vs baseline: 1.6682x; 1.6077x over previous
#include <cuda_runtime.h>
#include <math.h>
#include <float.h>
#include <stdint.h>

#define T_SEQ 2048
#define NH 16
#define HD 128
#define DIM 2048
#define QKV_DIM 6144
#define BQ 64
#define BKEY 64
#define KT_STRIDE 68
#define ATTN_SMEM ((BQ*HD + HD*KT_STRIDE + BKEY*HD + BQ*BKEY + 3*BQ) * 4)

typedef unsigned long long u64;

// ---- packed f32x2 primitives (attention) ----
__device__ __forceinline__ u64 ffma2(u64 a, u64 b, u64 c) {
    u64 d;
    asm("fma.rn.f32x2 %0, %1, %2, %3;" : "=l"(d) : "l"(a), "l"(b), "l"(c));
    return d;
}
__device__ __forceinline__ u64 fmul2(u64 a, u64 b) {
    u64 d;
    asm("mul.rn.f32x2 %0, %1, %2;" : "=l"(d) : "l"(a), "l"(b));
    return d;
}
__device__ __forceinline__ u64 pack2(float x, float y) {
    u64 r;
    asm("mov.b64 %0, {%1, %2};" : "=l"(r) : "f"(x), "f"(y));
    return r;
}
__device__ __forceinline__ float2 unpack2(u64 v) {
    float2 r;
    asm("mov.b64 {%0, %1}, %2;" : "=f"(r.x), "=f"(r.y) : "l"(v));
    return r;
}

// ---- mma.sync bf16 primitives (base ISA, works at compute_103) ----
__device__ __forceinline__ uint32_t smem_u32(const void* p) {
    uint32_t a;
    asm("{ .reg .u64 t; cvta.to.shared.u64 t, %1; cvt.u32.u64 %0, t; }"
        : "=r"(a) : "l"(p));
    return a;
}
__device__ __forceinline__ void ldsm4(uint32_t* r, uint32_t addr) {
    asm volatile("ldmatrix.sync.aligned.m8n8.x4.shared.b16 {%0,%1,%2,%3}, [%4];"
                 : "=r"(r[0]), "=r"(r[1]), "=r"(r[2]), "=r"(r[3]) : "r"(addr));
}
__device__ __forceinline__ void mma_bf16(float* c, const uint32_t* a, const uint32_t* b) {
    asm volatile(
        "mma.sync.aligned.m16n8k16.row.col.f32.bf16.bf16.f32 "
        "{%0,%1,%2,%3}, {%4,%5,%6,%7}, {%8,%9}, {%0,%1,%2,%3};"
        : "+f"(c[0]), "+f"(c[1]), "+f"(c[2]), "+f"(c[3])
        : "r"(a[0]), "r"(a[1]), "r"(a[2]), "r"(a[3]), "r"(b[0]), "r"(b[1]));
}
// pack truncated-bf16 of (x,y): result lo16 = hi-bits of x, hi16 = hi-bits of y
__device__ __forceinline__ uint32_t prmt_hi(float x, float y) {
    uint32_t r;
    asm("prmt.b32 %0, %1, %2, 0x7632;" : "=r"(r)
        : "r"(__float_as_uint(x)), "r"(__float_as_uint(y)));
    return r;
}
__device__ __forceinline__ float trunc_bf(float v) {
    return __uint_as_float(__float_as_uint(v) & 0xffff0000u);
}
__device__ __forceinline__ uint32_t cvt_bf2(float lo, float hi) {
    uint32_t r;
    asm("cvt.rn.bf16x2.f32 %0, %1, %2;" : "=r"(r) : "f"(hi), "f"(lo));
    return r;
}

// scratch
__device__ float g_qkv[2L * T_SEQ * QKV_DIM];
__device__ float g_att[2L * T_SEQ * DIM];

// ---------------------------------------------------------------------------
// bf16x3-split tensor-core GEMM: C[M,N] = A[M,K]*B[N,K]^T, fp32 in/out.
// CTA tile 128x128, 8 warps (2x4 of 64x32), BK=16, double-buffered smem.
// smem per buffer (24576 B): Ah(6144) Al(6144) Bh(6144) Bl(6144),
// each 128 rows x 16 bf16, row stride 24 elems (48 B, conflict-free LDSM).
// ---------------------------------------------------------------------------
#define GEMM_SMEM (2 * 24576)

__global__ __launch_bounds__(256) void gemm_bf16x3(const float* __restrict__ A,
                                                   const float* __restrict__ B,
                                                   float* __restrict__ C,
                                                   int N, int K) {
    extern __shared__ char sm[];
    uint32_t sb = smem_u32(sm);
    int tid = threadIdx.x, lane = tid & 31, wid = tid >> 5;
    int wm = wid >> 2, wn = wid & 3;

    const float* Ab = A + (size_t)blockIdx.y * 128 * K;
    const float* Bb = B + (size_t)blockIdx.x * 128 * K;

    // gmem load mapping: rows r0 and r0+64, 4 consecutive k at kq
    int r0 = tid >> 2;
    int kq = (tid & 3) * 4;
    uint32_t so0 = (uint32_t)(r0 * 48 + kq * 2);          // byte off in matrix
    uint32_t so1 = (uint32_t)((r0 + 64) * 48 + kq * 2);

    // LDSM source offsets (within buffer)
    uint32_t a_off = (uint32_t)((wm * 64 + (lane & 15)) * 48 + ((lane >> 4) * 8) * 2);
    uint32_t b_off = (uint32_t)((wn * 32 + (lane >> 4) * 8 + (lane & 7)) * 48 +
                                (((lane >> 3) & 1) * 8) * 2);

    float acc[4][4][4];
#pragma unroll
    for (int i = 0; i < 4; i++)
#pragma unroll
        for (int j = 0; j < 4; j++)
#pragma unroll
            for (int q = 0; q < 4; q++) acc[i][j][q] = 0.f;

    const int NC = K / 16;
    float4 pa0, pa1, pb0, pb1;

    // prefetch + stage chunk 0
    pa0 = *(const float4*)(Ab + (size_t)r0 * K + kq);
    pa1 = *(const float4*)(Ab + (size_t)(r0 + 64) * K + kq);
    pb0 = *(const float4*)(Bb + (size_t)r0 * K + kq);
    pb1 = *(const float4*)(Bb + (size_t)(r0 + 64) * K + kq);

#define STAGE(bufbase)                                                              \
    do {                                                                            \
        uint32_t _bb = (bufbase);                                                   \
        float4 v;                                                                   \
        uint32_t h01, h23, l01, l23;                                                \
        v = pa0;                                                                    \
        h01 = prmt_hi(v.x, v.y); h23 = prmt_hi(v.z, v.w);                           \
        l01 = cvt_bf2(v.x - trunc_bf(v.x), v.y - trunc_bf(v.y));                    \
        l23 = cvt_bf2(v.z - trunc_bf(v.z), v.w - trunc_bf(v.w));                    \
        asm volatile("st.shared.v2.u32 [%0], {%1,%2};" :: "r"(_bb + so0), "r"(h01), "r"(h23));          \
        asm volatile("st.shared.v2.u32 [%0], {%1,%2};" :: "r"(_bb + 6144 + so0), "r"(l01), "r"(l23));   \
        v = pa1;                                                                    \
        h01 = prmt_hi(v.x, v.y); h23 = prmt_hi(v.z, v.w);                           \
        l01 = cvt_bf2(v.x - trunc_bf(v.x), v.y - trunc_bf(v.y));                    \
        l23 = cvt_bf2(v.z - trunc_bf(v.z), v.w - trunc_bf(v.w));                    \
        asm volatile("st.shared.v2.u32 [%0], {%1,%2};" :: "r"(_bb + so1), "r"(h01), "r"(h23));          \
        asm volatile("st.shared.v2.u32 [%0], {%1,%2};" :: "r"(_bb + 6144 + so1), "r"(l01), "r"(l23));   \
        v = pb0;                                                                    \
        h01 = prmt_hi(v.x, v.y); h23 = prmt_hi(v.z, v.w);                           \
        l01 = cvt_bf2(v.x - trunc_bf(v.x), v.y - trunc_bf(v.y));                    \
        l23 = cvt_bf2(v.z - trunc_bf(v.z), v.w - trunc_bf(v.w));                    \
        asm volatile("st.shared.v2.u32 [%0], {%1,%2};" :: "r"(_bb + 12288 + so0), "r"(h01), "r"(h23));  \
        asm volatile("st.shared.v2.u32 [%0], {%1,%2};" :: "r"(_bb + 18432 + so0), "r"(l01), "r"(l23));  \
        v = pb1;                                                                    \
        h01 = prmt_hi(v.x, v.y); h23 = prmt_hi(v.z, v.w);                           \
        l01 = cvt_bf2(v.x - trunc_bf(v.x), v.y - trunc_bf(v.y));                    \
        l23 = cvt_bf2(v.z - trunc_bf(v.z), v.w - trunc_bf(v.w));                    \
        asm volatile("st.shared.v2.u32 [%0], {%1,%2};" :: "r"(_bb + 12288 + so1), "r"(h01), "r"(h23));  \
        asm volatile("st.shared.v2.u32 [%0], {%1,%2};" :: "r"(_bb + 18432 + so1), "r"(l01), "r"(l23));  \
    } while (0)

    STAGE(sb);
    __syncthreads();

    for (int c = 0; c < NC; ++c) {
        uint32_t base = sb + (uint32_t)(c & 1) * 24576;

        // prefetch next chunk from gmem (latency hidden behind MMAs)
        if (c + 1 < NC) {
            int k0 = (c + 1) * 16;
            pa0 = *(const float4*)(Ab + (size_t)r0 * K + k0 + kq);
            pa1 = *(const float4*)(Ab + (size_t)(r0 + 64) * K + k0 + kq);
            pb0 = *(const float4*)(Bb + (size_t)r0 * K + k0 + kq);
            pb1 = *(const float4*)(Bb + (size_t)(r0 + 64) * K + k0 + kq);
        }

        // fragments
        uint32_t AH[4][4], AL[4][4], BH[2][4], BL[2][4];
#pragma unroll
        for (int mt = 0; mt < 4; mt++) {
            uint32_t ad = base + a_off + mt * 768;   // 16 rows * 48B
            ldsm4(AH[mt], ad);
            ldsm4(AL[mt], ad + 6144);
        }
#pragma unroll
        for (int p = 0; p < 2; p++) {
            uint32_t bd = base + 12288 + b_off + p * 768;
            ldsm4(BH[p], bd);
            ldsm4(BL[p], bd + 6144);
        }

#pragma unroll
        for (int mt = 0; mt < 4; mt++)
#pragma unroll
            for (int nt = 0; nt < 4; nt++) {
                const uint32_t* bh = &BH[nt >> 1][(nt & 1) * 2];
                const uint32_t* bl = &BL[nt >> 1][(nt & 1) * 2];
                mma_bf16(acc[mt][nt], AH[mt], bh);
                mma_bf16(acc[mt][nt], AH[mt], bl);
                mma_bf16(acc[mt][nt], AL[mt], bh);
            }

        if (c + 1 < NC) {
            STAGE(sb + (uint32_t)((c + 1) & 1) * 24576);
            __syncthreads();
        }
    }

    // epilogue
    int g = lane >> 2, tg = lane & 3;
#pragma unroll
    for (int mt = 0; mt < 4; mt++) {
        int row = blockIdx.y * 128 + wm * 64 + mt * 16 + g;
#pragma unroll
        for (int nt = 0; nt < 4; nt++) {
            int col = blockIdx.x * 128 + wn * 32 + nt * 8 + tg * 2;
            *(float2*)(C + (size_t)row * N + col) =
                make_float2(acc[mt][nt][0], acc[mt][nt][1]);
            *(float2*)(C + (size_t)(row + 8) * N + col) =
                make_float2(acc[mt][nt][2], acc[mt][nt][3]);
        }
    }
}

// ---------------------------------------------------------------------------
// RoPE in-place on q and k halves of g_qkv.
// ---------------------------------------------------------------------------
__global__ __launch_bounds__(256) void rope_kernel() {
    int idx = blockIdx.x * 256 + threadIdx.x;
    int p = idx & 63;
    int h = (idx >> 6) & 15;
    int t = (idx >> 10) & 2047;
    int b = idx >> 21;

    float inv_freq = powf(10000.0f, -(float)p * (1.0f / 64.0f));
    float ang = (float)t * inv_freq;
    float s, c;
    sincosf(ang, &s, &c);

    size_t base = ((size_t)(b * T_SEQ + t)) * QKV_DIM + h * HD + p;
    float q1 = g_qkv[base], q2 = g_qkv[base + 64];
    g_qkv[base]      = q1 * c - q2 * s;
    g_qkv[base + 64] = q1 * s + q2 * c;
    float k1 = g_qkv[base + DIM], k2 = g_qkv[base + DIM + 64];
    g_qkv[base + DIM]      = k1 * c - k2 * s;
    g_qkv[base + DIM + 64] = k1 * s + k2 * c;
}

// ---------------------------------------------------------------------------
// Causal flash attention, fp32, f32x2 inner loops. (R2 passing version)
// ---------------------------------------------------------------------------
__global__ __launch_bounds__(256) void attn_kernel() {
    extern __shared__ float smf[];
    float* q_s  = smf;
    float* kT_s = q_s + BQ * HD;
    float* v_s  = kT_s + HD * KT_STRIDE;
    float* s_s  = v_s + BKEY * HD;
    float* m_s  = s_s + BQ * BKEY;
    float* l_s  = m_s + BQ;
    float* a_s  = l_s + BQ;

    int qt = blockIdx.x, h = blockIdx.y, b = blockIdx.z;
    int tid = threadIdx.x;
    int ty = tid >> 4, tx = tid & 15;
    int warp = tid >> 5, lane = tid & 31;

    const float* qbase = g_qkv + ((size_t)b * T_SEQ) * QKV_DIM + h * HD;
    const float* kbase = qbase + DIM;
    const float* vbase = qbase + 2 * DIM;
    int q0 = qt * BQ;

    for (int i = tid; i < BQ * (HD / 4); i += 256) {
        int r = i >> 5, c4 = (i & 31) * 4;
        *(float4*)&q_s[r * HD + c4] =
            *(const float4*)(qbase + (size_t)(q0 + r) * QKV_DIM + c4);
    }
    if (tid < BQ) { m_s[tid] = -1e30f; l_s[tid] = 0.f; }

    u64 o2[4][4];
#pragma unroll
    for (int i = 0; i < 4; i++)
#pragma unroll
        for (int j = 0; j < 4; j++) o2[i][j] = 0ull;

    const float scale = 0.08838834764831845f;

    for (int kt = 0; kt <= qt; ++kt) {
        int k0 = kt * BKEY;
        __syncthreads();

        for (int i = tid; i < BKEY * (HD / 4); i += 256) {
            int r = i >> 5, c4 = (i & 31) * 4;
            float4 kv = *(const float4*)(kbase + (size_t)(k0 + r) * QKV_DIM + c4);
            kT_s[(c4 + 0) * KT_STRIDE + r] = kv.x;
            kT_s[(c4 + 1) * KT_STRIDE + r] = kv.y;
            kT_s[(c4 + 2) * KT_STRIDE + r] = kv.z;
            kT_s[(c4 + 3) * KT_STRIDE + r] = kv.w;
        }
        for (int i = tid; i < BKEY * (HD / 4); i += 256) {
            int r = i >> 5, c4 = (i & 31) * 4;
            *(float4*)&v_s[r * HD + c4] =
                *(const float4*)(vbase + (size_t)(k0 + r) * QKV_DIM + c4);
        }
        __syncthreads();

        u64 s2[4][2];
#pragma unroll
        for (int i = 0; i < 4; i++) { s2[i][0] = 0ull; s2[i][1] = 0ull; }

        for (int d4 = 0; d4 < HD / 4; ++d4) {
            float4 qf[4];
#pragma unroll
            for (int i = 0; i < 4; i++)
                qf[i] = *(const float4*)&q_s[(ty * 4 + i) * HD + d4 * 4];
#pragma unroll
            for (int dd = 0; dd < 4; ++dd) {
                float4 kf = *(const float4*)&kT_s[(d4 * 4 + dd) * KT_STRIDE + tx * 4];
                u64 k01 = pack2(kf.x, kf.y);
                u64 k23 = pack2(kf.z, kf.w);
#pragma unroll
                for (int i = 0; i < 4; i++) {
                    float qv = ((const float*)&qf[i])[dd];
                    u64 qp = pack2(qv, qv);
                    s2[i][0] = ffma2(qp, k01, s2[i][0]);
                    s2[i][1] = ffma2(qp, k23, s2[i][1]);
                }
            }
        }

#pragma unroll
        for (int i = 0; i < 4; i++) {
            int qi = q0 + ty * 4 + i;
            float2 sa = unpack2(s2[i][0]);
            float2 sb2 = unpack2(s2[i][1]);
            float sv[4] = {sa.x, sa.y, sb2.x, sb2.y};
            float4 outv;
            float* op = (float*)&outv;
#pragma unroll
            for (int j = 0; j < 4; j++) {
                int kj = k0 + tx * 4 + j;
                op[j] = (kj > qi) ? -1e30f : sv[j] * scale;
            }
            *(float4*)&s_s[(ty * 4 + i) * BKEY + tx * 4] = outv;
        }
        __syncthreads();

        for (int rr = 0; rr < 8; ++rr) {
            int r = warp * 8 + rr;
            float x0 = s_s[r * BKEY + lane];
            float x1 = s_s[r * BKEY + 32 + lane];
            float mx = fmaxf(x0, x1);
#pragma unroll
            for (int off = 16; off > 0; off >>= 1)
                mx = fmaxf(mx, __shfl_xor_sync(0xffffffffu, mx, off));
            float mold = m_s[r];
            float mnew = fmaxf(mold, mx);
            float p0 = __expf(x0 - mnew);
            float p1 = __expf(x1 - mnew);
            s_s[r * BKEY + lane] = p0;
            s_s[r * BKEY + 32 + lane] = p1;
            float sum = p0 + p1;
#pragma unroll
            for (int off = 16; off > 0; off >>= 1)
                sum += __shfl_xor_sync(0xffffffffu, sum, off);
            if (lane == 0) {
                float alpha = __expf(mold - mnew);
                a_s[r] = alpha;
                m_s[r] = mnew;
                l_s[r] = l_s[r] * alpha + sum;
            }
        }
        __syncthreads();

#pragma unroll
        for (int i = 0; i < 4; i++) {
            u64 alp = pack2(a_s[ty * 4 + i], a_s[ty * 4 + i]);
#pragma unroll
            for (int j = 0; j < 4; j++) o2[i][j] = fmul2(o2[i][j], alp);
        }

        for (int k = 0; k < BKEY; k += 4) {
            float4 p4[4];
#pragma unroll
            for (int i = 0; i < 4; i++)
                p4[i] = *(const float4*)&s_s[(ty * 4 + i) * BKEY + k];
#pragma unroll
            for (int kk = 0; kk < 4; ++kk) {
                float4 va = *(const float4*)&v_s[(k + kk) * HD + tx * 8];
                float4 vb = *(const float4*)&v_s[(k + kk) * HD + tx * 8 + 4];
                u64 vv[4] = { pack2(va.x, va.y), pack2(va.z, va.w),
                              pack2(vb.x, vb.y), pack2(vb.z, vb.w) };
#pragma unroll
                for (int i = 0; i < 4; i++) {
                    float pv = ((const float*)&p4[i])[kk];
                    u64 pp = pack2(pv, pv);
#pragma unroll
                    for (int j = 0; j < 4; j++)
                        o2[i][j] = ffma2(pp, vv[j], o2[i][j]);
                }
            }
        }
    }

#pragma unroll
    for (int i = 0; i < 4; i++) {
        float inv = 1.0f / l_s[ty * 4 + i];
        float2 oa = unpack2(o2[i][0]), ob = unpack2(o2[i][1]);
        float2 oc = unpack2(o2[i][2]), od = unpack2(o2[i][3]);
        size_t off = ((size_t)(b * T_SEQ + q0 + ty * 4 + i)) * DIM + h * HD + tx * 8;
        *(float4*)&g_att[off] =
            make_float4(oa.x * inv, oa.y * inv, ob.x * inv, ob.y * inv);
        *(float4*)&g_att[off + 4] =
            make_float4(oc.x * inv, oc.y * inv, od.x * inv, od.y * inv);
    }
}

// ---------------------------------------------------------------------------
extern "C" void kernel_launch(void* const* d_in, const int* in_sizes, int n_in,
                              void* d_out, int out_size) {
    const float* x     = (const float*)d_in[0];  // [2,2048,2048]
    const float* w_qkv = (const float*)d_in[1];  // [6144,2048]
    const float* w_out = (const float*)d_in[2];  // [2048,2048]
    float* out = (float*)d_out;                  // [2,2048,2048]

    float* qkv_ptr = nullptr;
    float* att_ptr = nullptr;
    cudaGetSymbolAddress((void**)&qkv_ptr, g_qkv);
    cudaGetSymbolAddress((void**)&att_ptr, g_att);
    cudaFuncSetAttribute(attn_kernel, cudaFuncAttributeMaxDynamicSharedMemorySize, ATTN_SMEM);
    cudaFuncSetAttribute(gemm_bf16x3, cudaFuncAttributeMaxDynamicSharedMemorySize, GEMM_SMEM);

    // 1) QKV projection: [4096,2048] x [6144,2048]^T  (bf16x3 tensor cores)
    gemm_bf16x3<<<dim3(QKV_DIM / 128, 4096 / 128), 256, GEMM_SMEM>>>(x, w_qkv, qkv_ptr, QKV_DIM, DIM);
    // 2) RoPE
    rope_kernel<<<(2 * T_SEQ * NH * 64) / 256, 256>>>();
    // 3) causal attention
    attn_kernel<<<dim3(T_SEQ / BQ, NH, 2), 256, ATTN_SMEM>>>();
    // 4) output projection: [4096,2048] x [2048,2048]^T  (bf16x3 tensor cores)
    gemm_bf16x3<<<dim3(DIM / 128, 4096 / 128), 256, GEMM_SMEM>>>(att_ptr, w_out, out, DIM, DIM);
}

// round 5
// speedup vs baseline: 3.0708x; 1.8408x over previous
#include <cuda_runtime.h>
#include <cuda_bf16.h>
#include <math.h>
#include <float.h>
#include <stdint.h>

#define T_SEQ 2048
#define NH 16
#define HD 128
#define DIM 2048
#define QKV_DIM 6144

// ---- mma.sync bf16 primitives (base ISA, works at compute_103) ----
__device__ __forceinline__ uint32_t smem_u32(const void* p) {
    uint32_t a;
    asm("{ .reg .u64 t; cvta.to.shared.u64 t, %1; cvt.u32.u64 %0, t; }"
        : "=r"(a) : "l"(p));
    return a;
}
__device__ __forceinline__ void ldsm4(uint32_t* r, uint32_t addr) {
    asm volatile("ldmatrix.sync.aligned.m8n8.x4.shared.b16 {%0,%1,%2,%3}, [%4];"
                 : "=r"(r[0]), "=r"(r[1]), "=r"(r[2]), "=r"(r[3]) : "r"(addr));
}
__device__ __forceinline__ void ldsm4t(uint32_t* r, uint32_t addr) {
    asm volatile("ldmatrix.sync.aligned.m8n8.x4.trans.shared.b16 {%0,%1,%2,%3}, [%4];"
                 : "=r"(r[0]), "=r"(r[1]), "=r"(r[2]), "=r"(r[3]) : "r"(addr));
}
__device__ __forceinline__ void mma_bf16(float* c, const uint32_t* a, const uint32_t* b) {
    asm volatile(
        "mma.sync.aligned.m16n8k16.row.col.f32.bf16.bf16.f32 "
        "{%0,%1,%2,%3}, {%4,%5,%6,%7}, {%8,%9}, {%0,%1,%2,%3};"
        : "+f"(c[0]), "+f"(c[1]), "+f"(c[2]), "+f"(c[3])
        : "r"(a[0]), "r"(a[1]), "r"(a[2]), "r"(a[3]), "r"(b[0]), "r"(b[1]));
}
__device__ __forceinline__ uint32_t prmt_hi(float x, float y) {
    uint32_t r;
    asm("prmt.b32 %0, %1, %2, 0x7632;" : "=r"(r)
        : "r"(__float_as_uint(x)), "r"(__float_as_uint(y)));
    return r;
}
__device__ __forceinline__ float trunc_bf(float v) {
    return __uint_as_float(__float_as_uint(v) & 0xffff0000u);
}
__device__ __forceinline__ uint32_t cvt_bf2(float lo, float hi) {
    uint32_t r;
    asm("cvt.rn.bf16x2.f32 %0, %1, %2;" : "=r"(r) : "f"(hi), "f"(lo));
    return r;
}

// scratch
__device__ float g_qkv[2L * T_SEQ * QKV_DIM];
__device__ float g_att[2L * T_SEQ * DIM];
// pre-split bf16 Q/K/V, head-contiguous: [b][h][t][d]
__device__ __nv_bfloat16 g_qh[2L * NH * T_SEQ * HD];
__device__ __nv_bfloat16 g_ql[2L * NH * T_SEQ * HD];
__device__ __nv_bfloat16 g_kh[2L * NH * T_SEQ * HD];
__device__ __nv_bfloat16 g_kl[2L * NH * T_SEQ * HD];
__device__ __nv_bfloat16 g_vh[2L * NH * T_SEQ * HD];
__device__ __nv_bfloat16 g_vl[2L * NH * T_SEQ * HD];

// ---------------------------------------------------------------------------
// bf16x3-split tensor-core GEMM (unchanged from R4 passing version).
// ---------------------------------------------------------------------------
#define GEMM_SMEM (2 * 24576)

__global__ __launch_bounds__(256) void gemm_bf16x3(const float* __restrict__ A,
                                                   const float* __restrict__ B,
                                                   float* __restrict__ C,
                                                   int N, int K) {
    extern __shared__ char sm[];
    uint32_t sb = smem_u32(sm);
    int tid = threadIdx.x, lane = tid & 31, wid = tid >> 5;
    int wm = wid >> 2, wn = wid & 3;

    const float* Ab = A + (size_t)blockIdx.y * 128 * K;
    const float* Bb = B + (size_t)blockIdx.x * 128 * K;

    int r0 = tid >> 2;
    int kq = (tid & 3) * 4;
    uint32_t so0 = (uint32_t)(r0 * 48 + kq * 2);
    uint32_t so1 = (uint32_t)((r0 + 64) * 48 + kq * 2);

    uint32_t a_off = (uint32_t)((wm * 64 + (lane & 15)) * 48 + ((lane >> 4) * 8) * 2);
    uint32_t b_off = (uint32_t)((wn * 32 + (lane >> 4) * 8 + (lane & 7)) * 48 +
                                (((lane >> 3) & 1) * 8) * 2);

    float acc[4][4][4];
#pragma unroll
    for (int i = 0; i < 4; i++)
#pragma unroll
        for (int j = 0; j < 4; j++)
#pragma unroll
            for (int q = 0; q < 4; q++) acc[i][j][q] = 0.f;

    const int NC = K / 16;
    float4 pa0, pa1, pb0, pb1;

    pa0 = *(const float4*)(Ab + (size_t)r0 * K + kq);
    pa1 = *(const float4*)(Ab + (size_t)(r0 + 64) * K + kq);
    pb0 = *(const float4*)(Bb + (size_t)r0 * K + kq);
    pb1 = *(const float4*)(Bb + (size_t)(r0 + 64) * K + kq);

#define STAGE(bufbase)                                                              \
    do {                                                                            \
        uint32_t _bb = (bufbase);                                                   \
        float4 v;                                                                   \
        uint32_t h01, h23, l01, l23;                                                \
        v = pa0;                                                                    \
        h01 = prmt_hi(v.x, v.y); h23 = prmt_hi(v.z, v.w);                           \
        l01 = cvt_bf2(v.x - trunc_bf(v.x), v.y - trunc_bf(v.y));                    \
        l23 = cvt_bf2(v.z - trunc_bf(v.z), v.w - trunc_bf(v.w));                    \
        asm volatile("st.shared.v2.u32 [%0], {%1,%2};" :: "r"(_bb + so0), "r"(h01), "r"(h23));          \
        asm volatile("st.shared.v2.u32 [%0], {%1,%2};" :: "r"(_bb + 6144 + so0), "r"(l01), "r"(l23));   \
        v = pa1;                                                                    \
        h01 = prmt_hi(v.x, v.y); h23 = prmt_hi(v.z, v.w);                           \
        l01 = cvt_bf2(v.x - trunc_bf(v.x), v.y - trunc_bf(v.y));                    \
        l23 = cvt_bf2(v.z - trunc_bf(v.z), v.w - trunc_bf(v.w));                    \
        asm volatile("st.shared.v2.u32 [%0], {%1,%2};" :: "r"(_bb + so1), "r"(h01), "r"(h23));          \
        asm volatile("st.shared.v2.u32 [%0], {%1,%2};" :: "r"(_bb + 6144 + so1), "r"(l01), "r"(l23));   \
        v = pb0;                                                                    \
        h01 = prmt_hi(v.x, v.y); h23 = prmt_hi(v.z, v.w);                           \
        l01 = cvt_bf2(v.x - trunc_bf(v.x), v.y - trunc_bf(v.y));                    \
        l23 = cvt_bf2(v.z - trunc_bf(v.z), v.w - trunc_bf(v.w));                    \
        asm volatile("st.shared.v2.u32 [%0], {%1,%2};" :: "r"(_bb + 12288 + so0), "r"(h01), "r"(h23));  \
        asm volatile("st.shared.v2.u32 [%0], {%1,%2};" :: "r"(_bb + 18432 + so0), "r"(l01), "r"(l23));  \
        v = pb1;                                                                    \
        h01 = prmt_hi(v.x, v.y); h23 = prmt_hi(v.z, v.w);                           \
        l01 = cvt_bf2(v.x - trunc_bf(v.x), v.y - trunc_bf(v.y));                    \
        l23 = cvt_bf2(v.z - trunc_bf(v.z), v.w - trunc_bf(v.w));                    \
        asm volatile("st.shared.v2.u32 [%0], {%1,%2};" :: "r"(_bb + 12288 + so1), "r"(h01), "r"(h23));  \
        asm volatile("st.shared.v2.u32 [%0], {%1,%2};" :: "r"(_bb + 18432 + so1), "r"(l01), "r"(l23));  \
    } while (0)

    STAGE(sb);
    __syncthreads();

    for (int c = 0; c < NC; ++c) {
        uint32_t base = sb + (uint32_t)(c & 1) * 24576;

        if (c + 1 < NC) {
            int k0 = (c + 1) * 16;
            pa0 = *(const float4*)(Ab + (size_t)r0 * K + k0 + kq);
            pa1 = *(const float4*)(Ab + (size_t)(r0 + 64) * K + k0 + kq);
            pb0 = *(const float4*)(Bb + (size_t)r0 * K + k0 + kq);
            pb1 = *(const float4*)(Bb + (size_t)(r0 + 64) * K + k0 + kq);
        }

        uint32_t AH[4][4], AL[4][4], BH[2][4], BL[2][4];
#pragma unroll
        for (int mt = 0; mt < 4; mt++) {
            uint32_t ad = base + a_off + mt * 768;
            ldsm4(AH[mt], ad);
            ldsm4(AL[mt], ad + 6144);
        }
#pragma unroll
        for (int p = 0; p < 2; p++) {
            uint32_t bd = base + 12288 + b_off + p * 768;
            ldsm4(BH[p], bd);
            ldsm4(BL[p], bd + 6144);
        }

#pragma unroll
        for (int mt = 0; mt < 4; mt++)
#pragma unroll
            for (int nt = 0; nt < 4; nt++) {
                const uint32_t* bh = &BH[nt >> 1][(nt & 1) * 2];
                const uint32_t* bl = &BL[nt >> 1][(nt & 1) * 2];
                mma_bf16(acc[mt][nt], AH[mt], bh);
                mma_bf16(acc[mt][nt], AH[mt], bl);
                mma_bf16(acc[mt][nt], AL[mt], bh);
            }

        if (c + 1 < NC) {
            STAGE(sb + (uint32_t)((c + 1) & 1) * 24576);
            __syncthreads();
        }
    }

    int g = lane >> 2, tg = lane & 3;
#pragma unroll
    for (int mt = 0; mt < 4; mt++) {
        int row = blockIdx.y * 128 + wm * 64 + mt * 16 + g;
#pragma unroll
        for (int nt = 0; nt < 4; nt++) {
            int col = blockIdx.x * 128 + wn * 32 + nt * 8 + tg * 2;
            *(float2*)(C + (size_t)row * N + col) =
                make_float2(acc[mt][nt][0], acc[mt][nt][1]);
            *(float2*)(C + (size_t)(row + 8) * N + col) =
                make_float2(acc[mt][nt][2], acc[mt][nt][3]);
        }
    }
}

// ---------------------------------------------------------------------------
// RoPE + bf16 hi/lo split of Q,K,V into head-contiguous scratch.
// One thread per (b,t,h,p), p in [0,64).
// ---------------------------------------------------------------------------
__device__ __forceinline__ void split_store(float x, __nv_bfloat16* ph, __nv_bfloat16* pl) {
    uint32_t hb = __float_as_uint(x) & 0xffff0000u;
    *(unsigned short*)ph = (unsigned short)(hb >> 16);
    *pl = __float2bfloat16(x - __uint_as_float(hb));
}

__global__ __launch_bounds__(256) void rope_convert() {
    int idx = blockIdx.x * 256 + threadIdx.x;
    int p = idx & 63;
    int h = (idx >> 6) & 15;
    int t = (idx >> 10) & 2047;
    int b = idx >> 21;

    float inv_freq = powf(10000.0f, -(float)p * (1.0f / 64.0f));
    float ang = (float)t * inv_freq;
    float s, c;
    sincosf(ang, &s, &c);

    size_t src = ((size_t)(b * T_SEQ + t)) * QKV_DIM + h * HD + p;
    size_t dst = ((size_t)((b * NH + h) * T_SEQ) + t) * HD + p;

    float q1 = g_qkv[src], q2 = g_qkv[src + 64];
    float qr1 = q1 * c - q2 * s, qr2 = q1 * s + q2 * c;
    split_store(qr1, &g_qh[dst], &g_ql[dst]);
    split_store(qr2, &g_qh[dst + 64], &g_ql[dst + 64]);

    float k1 = g_qkv[src + DIM], k2 = g_qkv[src + DIM + 64];
    float kr1 = k1 * c - k2 * s, kr2 = k1 * s + k2 * c;
    split_store(kr1, &g_kh[dst], &g_kl[dst]);
    split_store(kr2, &g_kh[dst + 64], &g_kl[dst + 64]);

    float v1 = g_qkv[src + 2 * DIM], v2 = g_qkv[src + 2 * DIM + 64];
    split_store(v1, &g_vh[dst], &g_vl[dst]);
    split_store(v2, &g_vh[dst + 64], &g_vl[dst + 64]);
}

// ---------------------------------------------------------------------------
// Tensor-core causal flash attention (bf16x3 split, fragment softmax).
// CTA = 128 threads (4 warps), per (q-tile 64, head, batch).
// Warp w owns q rows [w*16, w*16+16).
// ---------------------------------------------------------------------------
#define SST 272                 // bytes per smem row (136 bf16)
#define O_QH 0
#define O_QL 17408
#define O_KH 34816
#define O_KL 52224
#define O_VH 69632
#define O_VL 87040
#define ATTN_SMEM2 104448

__global__ __launch_bounds__(128) void attn_mma() {
    extern __shared__ char sm[];
    uint32_t sb = smem_u32(sm);
    int tid = threadIdx.x, lane = tid & 31, w = tid >> 5;
    int qt = blockIdx.x, h = blockIdx.y, b = blockIdx.z;
    int q0 = qt * 64;
    size_t hb = ((size_t)(b * NH + h)) * T_SEQ;

    // load Q hi/lo tile [64][128] bf16
    {
        const char* qh_g = (const char*)(g_qh + (hb + q0) * HD);
        const char* ql_g = (const char*)(g_ql + (hb + q0) * HD);
#pragma unroll
        for (int i = 0; i < 8; i++) {
            int idx = tid + i * 128;
            int r = idx >> 4, ch = idx & 15;
            int so = r * SST + ch * 16, go = r * 256 + ch * 16;
            *(uint4*)(sm + O_QH + so) = *(const uint4*)(qh_g + go);
            *(uint4*)(sm + O_QL + so) = *(const uint4*)(ql_g + go);
        }
    }

    int g = lane >> 2, tg = lane & 3;
    uint32_t q_off = (uint32_t)((w * 16 + (lane & 15)) * SST + ((lane >> 4) * 8) * 2);
    uint32_t kb_off = (uint32_t)((((lane >> 4) * 8) + (lane & 7)) * SST +
                                 (((lane >> 3) & 1) * 8) * 2);
    uint32_t v_off = (uint32_t)((lane & 15) * SST + ((lane >> 4) * 8) * 2);

    float o[16][4];
#pragma unroll
    for (int i = 0; i < 16; i++)
#pragma unroll
        for (int j = 0; j < 4; j++) o[i][j] = 0.f;

    float m0 = -1e30f, m1 = -1e30f, l0 = 0.f, l1 = 0.f;
    const float scale = 0.08838834764831845f;  // 1/sqrt(128)

    for (int kt = 0; kt <= qt; ++kt) {
        int k0 = kt * 64;
        __syncthreads();
        {
            const char* kh_g = (const char*)(g_kh + (hb + k0) * HD);
            const char* kl_g = (const char*)(g_kl + (hb + k0) * HD);
            const char* vh_g = (const char*)(g_vh + (hb + k0) * HD);
            const char* vl_g = (const char*)(g_vl + (hb + k0) * HD);
#pragma unroll
            for (int i = 0; i < 8; i++) {
                int idx = tid + i * 128;
                int r = idx >> 4, ch = idx & 15;
                int so = r * SST + ch * 16, go = r * 256 + ch * 16;
                *(uint4*)(sm + O_KH + so) = *(const uint4*)(kh_g + go);
                *(uint4*)(sm + O_KL + so) = *(const uint4*)(kl_g + go);
                *(uint4*)(sm + O_VH + so) = *(const uint4*)(vh_g + go);
                *(uint4*)(sm + O_VL + so) = *(const uint4*)(vl_g + go);
            }
        }
        __syncthreads();

        // S = Q K^T (16 rows x 64 keys per warp), bf16x3
        float st[8][4];
#pragma unroll
        for (int i = 0; i < 8; i++)
#pragma unroll
            for (int j = 0; j < 4; j++) st[i][j] = 0.f;

#pragma unroll
        for (int ks = 0; ks < 8; ++ks) {
            uint32_t AH4[4], AL4[4];
            ldsm4(AH4, sb + O_QH + q_off + ks * 32);
            ldsm4(AL4, sb + O_QL + q_off + ks * 32);
#pragma unroll
            for (int p = 0; p < 4; ++p) {
                uint32_t BH4[4], BL4[4];
                uint32_t ko = kb_off + p * 16 * SST + ks * 32;
                ldsm4(BH4, sb + O_KH + ko);
                ldsm4(BL4, sb + O_KL + ko);
                mma_bf16(st[2 * p], AH4, BH4);
                mma_bf16(st[2 * p], AH4, BL4);
                mma_bf16(st[2 * p], AL4, BH4);
                mma_bf16(st[2 * p + 1], AH4, BH4 + 2);
                mma_bf16(st[2 * p + 1], AH4, BL4 + 2);
                mma_bf16(st[2 * p + 1], AL4, BH4 + 2);
            }
        }

        // fragment-level online softmax (rows g and g+8 of this warp's 16)
        int rowg = q0 + w * 16 + g;
        bool diag = (kt == qt);
        float mx0 = -1e30f, mx1 = -1e30f;
#pragma unroll
        for (int nt = 0; nt < 8; ++nt) {
            int c0 = k0 + nt * 8 + 2 * tg;
            st[nt][0] *= scale; st[nt][1] *= scale;
            st[nt][2] *= scale; st[nt][3] *= scale;
            if (diag) {
                if (c0 > rowg)         st[nt][0] = -1e30f;
                if (c0 + 1 > rowg)     st[nt][1] = -1e30f;
                if (c0 > rowg + 8)     st[nt][2] = -1e30f;
                if (c0 + 1 > rowg + 8) st[nt][3] = -1e30f;
            }
            mx0 = fmaxf(mx0, fmaxf(st[nt][0], st[nt][1]));
            mx1 = fmaxf(mx1, fmaxf(st[nt][2], st[nt][3]));
        }
        mx0 = fmaxf(mx0, __shfl_xor_sync(0xffffffffu, mx0, 1));
        mx0 = fmaxf(mx0, __shfl_xor_sync(0xffffffffu, mx0, 2));
        mx1 = fmaxf(mx1, __shfl_xor_sync(0xffffffffu, mx1, 1));
        mx1 = fmaxf(mx1, __shfl_xor_sync(0xffffffffu, mx1, 2));

        float mn0 = fmaxf(m0, mx0), mn1 = fmaxf(m1, mx1);
        float al0 = __expf(m0 - mn0), al1 = __expf(m1 - mn1);
        float s0 = 0.f, s1 = 0.f;
#pragma unroll
        for (int nt = 0; nt < 8; ++nt) {
            st[nt][0] = __expf(st[nt][0] - mn0);
            st[nt][1] = __expf(st[nt][1] - mn0);
            st[nt][2] = __expf(st[nt][2] - mn1);
            st[nt][3] = __expf(st[nt][3] - mn1);
            s0 += st[nt][0] + st[nt][1];
            s1 += st[nt][2] + st[nt][3];
        }
        s0 += __shfl_xor_sync(0xffffffffu, s0, 1);
        s0 += __shfl_xor_sync(0xffffffffu, s0, 2);
        s1 += __shfl_xor_sync(0xffffffffu, s1, 1);
        s1 += __shfl_xor_sync(0xffffffffu, s1, 2);
        l0 = l0 * al0 + s0;
        l1 = l1 * al1 + s1;
        m0 = mn0; m1 = mn1;

#pragma unroll
        for (int i = 0; i < 16; i++) {
            o[i][0] *= al0; o[i][1] *= al0;
            o[i][2] *= al1; o[i][3] *= al1;
        }

        // O += P V (bf16x3 split of P and V)
#pragma unroll
        for (int ks = 0; ks < 4; ++ks) {
            float e0 = st[2 * ks][0], e1 = st[2 * ks][1];
            float e2 = st[2 * ks][2], e3 = st[2 * ks][3];
            float f0 = st[2 * ks + 1][0], f1 = st[2 * ks + 1][1];
            float f2 = st[2 * ks + 1][2], f3 = st[2 * ks + 1][3];
            uint32_t PH[4], PL[4];
            PH[0] = prmt_hi(e0, e1); PH[1] = prmt_hi(e2, e3);
            PH[2] = prmt_hi(f0, f1); PH[3] = prmt_hi(f2, f3);
            PL[0] = cvt_bf2(e0 - trunc_bf(e0), e1 - trunc_bf(e1));
            PL[1] = cvt_bf2(e2 - trunc_bf(e2), e3 - trunc_bf(e3));
            PL[2] = cvt_bf2(f0 - trunc_bf(f0), f1 - trunc_bf(f1));
            PL[3] = cvt_bf2(f2 - trunc_bf(f2), f3 - trunc_bf(f3));
#pragma unroll
            for (int np = 0; np < 8; ++np) {
                uint32_t VH4[4], VL4[4];
                uint32_t vo = v_off + ks * 16 * SST + np * 32;
                ldsm4t(VH4, sb + O_VH + vo);
                ldsm4t(VL4, sb + O_VL + vo);
                mma_bf16(o[2 * np], PH, VH4);
                mma_bf16(o[2 * np], PL, VH4);
                mma_bf16(o[2 * np], PH, VL4);
                mma_bf16(o[2 * np + 1], PH, VH4 + 2);
                mma_bf16(o[2 * np + 1], PL, VH4 + 2);
                mma_bf16(o[2 * np + 1], PH, VL4 + 2);
            }
        }
    }

    // finalize
    float inv0 = 1.f / l0, inv1 = 1.f / l1;
    int r0 = q0 + w * 16 + g;
    float* orow0 = g_att + ((size_t)(b * T_SEQ) + r0) * DIM + h * HD;
    float* orow1 = orow0 + (size_t)8 * DIM;
#pragma unroll
    for (int np = 0; np < 16; ++np) {
        int col = np * 8 + 2 * tg;
        *(float2*)(orow0 + col) = make_float2(o[np][0] * inv0, o[np][1] * inv0);
        *(float2*)(orow1 + col) = make_float2(o[np][2] * inv1, o[np][3] * inv1);
    }
}

// ---------------------------------------------------------------------------
extern "C" void kernel_launch(void* const* d_in, const int* in_sizes, int n_in,
                              void* d_out, int out_size) {
    const float* x     = (const float*)d_in[0];  // [2,2048,2048]
    const float* w_qkv = (const float*)d_in[1];  // [6144,2048]
    const float* w_out = (const float*)d_in[2];  // [2048,2048]
    float* out = (float*)d_out;                  // [2,2048,2048]

    float* qkv_ptr = nullptr;
    float* att_ptr = nullptr;
    cudaGetSymbolAddress((void**)&qkv_ptr, g_qkv);
    cudaGetSymbolAddress((void**)&att_ptr, g_att);
    cudaFuncSetAttribute(gemm_bf16x3, cudaFuncAttributeMaxDynamicSharedMemorySize, GEMM_SMEM);
    cudaFuncSetAttribute(attn_mma, cudaFuncAttributeMaxDynamicSharedMemorySize, ATTN_SMEM2);

    // 1) QKV projection (tensor cores, bf16x3)
    gemm_bf16x3<<<dim3(QKV_DIM / 128, 4096 / 128), 256, GEMM_SMEM>>>(x, w_qkv, qkv_ptr, QKV_DIM, DIM);
    // 2) RoPE + bf16 hi/lo split of Q,K,V
    rope_convert<<<(2 * T_SEQ * NH * 64) / 256, 256>>>();
    // 3) causal attention (tensor cores, bf16x3)
    attn_mma<<<dim3(T_SEQ / 64, NH, 2), 128, ATTN_SMEM2>>>();
    // 4) output projection (tensor cores, bf16x3)
    gemm_bf16x3<<<dim3(DIM / 128, 4096 / 128), 256, GEMM_SMEM>>>(att_ptr, w_out, out, DIM, DIM);
}

// round 6
// speedup vs baseline: 3.2195x; 1.0484x over previous
#include <cuda_runtime.h>
#include <cuda_bf16.h>
#include <math.h>
#include <float.h>
#include <stdint.h>

#define T_SEQ 2048
#define NH 16
#define HD 128
#define DIM 2048
#define QKV_DIM 6144

// ---- mma.sync bf16 primitives (base ISA, works at compute_103) ----
__device__ __forceinline__ uint32_t smem_u32(const void* p) {
    uint32_t a;
    asm("{ .reg .u64 t; cvta.to.shared.u64 t, %1; cvt.u32.u64 %0, t; }"
        : "=r"(a) : "l"(p));
    return a;
}
__device__ __forceinline__ void ldsm4(uint32_t* r, uint32_t addr) {
    asm volatile("ldmatrix.sync.aligned.m8n8.x4.shared.b16 {%0,%1,%2,%3}, [%4];"
                 : "=r"(r[0]), "=r"(r[1]), "=r"(r[2]), "=r"(r[3]) : "r"(addr));
}
__device__ __forceinline__ void ldsm4t(uint32_t* r, uint32_t addr) {
    asm volatile("ldmatrix.sync.aligned.m8n8.x4.trans.shared.b16 {%0,%1,%2,%3}, [%4];"
                 : "=r"(r[0]), "=r"(r[1]), "=r"(r[2]), "=r"(r[3]) : "r"(addr));
}
__device__ __forceinline__ void mma_bf16(float* c, const uint32_t* a, const uint32_t* b) {
    asm volatile(
        "mma.sync.aligned.m16n8k16.row.col.f32.bf16.bf16.f32 "
        "{%0,%1,%2,%3}, {%4,%5,%6,%7}, {%8,%9}, {%0,%1,%2,%3};"
        : "+f"(c[0]), "+f"(c[1]), "+f"(c[2]), "+f"(c[3])
        : "r"(a[0]), "r"(a[1]), "r"(a[2]), "r"(a[3]), "r"(b[0]), "r"(b[1]));
}
__device__ __forceinline__ uint32_t prmt_hi(float x, float y) {
    uint32_t r;
    asm("prmt.b32 %0, %1, %2, 0x7632;" : "=r"(r)
        : "r"(__float_as_uint(x)), "r"(__float_as_uint(y)));
    return r;
}
__device__ __forceinline__ float trunc_bf(float v) {
    return __uint_as_float(__float_as_uint(v) & 0xffff0000u);
}
__device__ __forceinline__ uint32_t cvt_bf2(float lo, float hi) {
    uint32_t r;
    asm("cvt.rn.bf16x2.f32 %0, %1, %2;" : "=r"(r) : "f"(hi), "f"(lo));
    return r;
}
__device__ __forceinline__ void cp_async16(uint32_t saddr, const void* gptr) {
    asm volatile("cp.async.cg.shared.global [%0], [%1], 16;" :: "r"(saddr), "l"(gptr));
}
#define CP_COMMIT() asm volatile("cp.async.commit_group;" ::: "memory")
#define CP_WAIT(n)  asm volatile("cp.async.wait_group %0;" :: "n"(n) : "memory")

// scratch
__device__ float g_qkv[2L * T_SEQ * QKV_DIM];
__device__ float g_att[2L * T_SEQ * DIM];
__device__ __nv_bfloat16 g_qh[2L * NH * T_SEQ * HD];
__device__ __nv_bfloat16 g_ql[2L * NH * T_SEQ * HD];
__device__ __nv_bfloat16 g_kh[2L * NH * T_SEQ * HD];
__device__ __nv_bfloat16 g_kl[2L * NH * T_SEQ * HD];
__device__ __nv_bfloat16 g_vh[2L * NH * T_SEQ * HD];
__device__ __nv_bfloat16 g_vl[2L * NH * T_SEQ * HD];

// ---------------------------------------------------------------------------
// bf16x3-split tensor-core GEMM with cp.async staging + 2 CTAs/SM.
// C[M,N] = A[M,K]*B[N,K]^T, fp32 in/out. 128x128 tile, 8 warps of 64x32.
// smem: raw fp32 A/B (double buf) + bf16 split Ah/Al/Bh/Bl (double buf).
// ---------------------------------------------------------------------------
#define GS_RAWA(b) ((b) * 8192)
#define GS_RAWB(b) (16384 + (b) * 8192)
#define GS_SPL(b)  (32768 + (b) * 24576)   // Ah; +6144 Al; +12288 Bh; +18432 Bl
#define GEMM_SMEM  (32768 + 2 * 24576)     // 81920 B

__global__ __launch_bounds__(256, 2) void gemm_bf16x3(const float* __restrict__ A,
                                                      const float* __restrict__ B,
                                                      float* __restrict__ C,
                                                      int N, int K) {
    extern __shared__ char sm[];
    uint32_t sb = smem_u32(sm);
    int tid = threadIdx.x, lane = tid & 31, wid = tid >> 5;
    int wm = wid >> 2, wn = wid & 3;

    const float* Ab = A + (size_t)blockIdx.y * 128 * K;
    const float* Bb = B + (size_t)blockIdx.x * 128 * K;

    // cp.async mapping: thread copies 32B of one row (row = tid>>1)
    int cprow = tid >> 1;
    int cpcol = (tid & 1) * 8;            // float offset within 16-float row
    uint32_t cpso = (uint32_t)(cprow * 64 + cpcol * 4);

    // ldsm offsets within split buffer (48-B rows)
    uint32_t a_off = (uint32_t)((wm * 64 + (lane & 15)) * 48 + ((lane >> 4) * 8) * 2);
    uint32_t b_off = (uint32_t)((wn * 32 + (lane >> 4) * 8 + (lane & 7)) * 48 +
                                (((lane >> 3) & 1) * 8) * 2);

    float acc[4][4][4];
#pragma unroll
    for (int i = 0; i < 4; i++)
#pragma unroll
        for (int j = 0; j < 4; j++)
#pragma unroll
            for (int q = 0; q < 4; q++) acc[i][j][q] = 0.f;

    const int NC = K / 16;

    // prologue: cp.async chunk 0 -> raw[0]
    {
        const float* ga = Ab + (size_t)cprow * K + cpcol;
        const float* gb = Bb + (size_t)cprow * K + cpcol;
        cp_async16(sb + GS_RAWA(0) + cpso, ga);
        cp_async16(sb + GS_RAWA(0) + cpso + 16, ga + 4);
        cp_async16(sb + GS_RAWB(0) + cpso, gb);
        cp_async16(sb + GS_RAWB(0) + cpso + 16, gb + 4);
        CP_COMMIT();
    }

    for (int c = 0; c < NC; ++c) {
        int buf = c & 1;

        if (c + 1 < NC) {
            int k0 = (c + 1) * 16;
            const float* ga = Ab + (size_t)cprow * K + k0 + cpcol;
            const float* gb = Bb + (size_t)cprow * K + k0 + cpcol;
            int nb = buf ^ 1;
            cp_async16(sb + GS_RAWA(nb) + cpso, ga);
            cp_async16(sb + GS_RAWA(nb) + cpso + 16, ga + 4);
            cp_async16(sb + GS_RAWB(nb) + cpso, gb);
            cp_async16(sb + GS_RAWB(nb) + cpso + 16, gb + 4);
            CP_COMMIT();
            CP_WAIT(1);
        } else {
            CP_WAIT(0);
        }
        __syncthreads();

        // convert raw[buf] fp32 -> bf16 hi/lo split[buf]
        {
            uint32_t spl = sb + GS_SPL(buf);
#pragma unroll
            for (int i = 0; i < 2; ++i) {
                int idx = tid + i * 256;          // 0..511
                int row = idx >> 2, sl = idx & 3;
                uint32_t ro = (uint32_t)(row * 64 + sl * 16);
                uint32_t so = (uint32_t)(row * 48 + sl * 8);
                float4 v = *(const float4*)(sm + GS_RAWA(buf) + ro);
                uint32_t h01 = prmt_hi(v.x, v.y), h23 = prmt_hi(v.z, v.w);
                uint32_t l01 = cvt_bf2(v.x - trunc_bf(v.x), v.y - trunc_bf(v.y));
                uint32_t l23 = cvt_bf2(v.z - trunc_bf(v.z), v.w - trunc_bf(v.w));
                asm volatile("st.shared.v2.u32 [%0], {%1,%2};" :: "r"(spl + so), "r"(h01), "r"(h23));
                asm volatile("st.shared.v2.u32 [%0], {%1,%2};" :: "r"(spl + 6144 + so), "r"(l01), "r"(l23));
                v = *(const float4*)(sm + GS_RAWB(buf) + ro);
                h01 = prmt_hi(v.x, v.y); h23 = prmt_hi(v.z, v.w);
                l01 = cvt_bf2(v.x - trunc_bf(v.x), v.y - trunc_bf(v.y));
                l23 = cvt_bf2(v.z - trunc_bf(v.z), v.w - trunc_bf(v.w));
                asm volatile("st.shared.v2.u32 [%0], {%1,%2};" :: "r"(spl + 12288 + so), "r"(h01), "r"(h23));
                asm volatile("st.shared.v2.u32 [%0], {%1,%2};" :: "r"(spl + 18432 + so), "r"(l01), "r"(l23));
            }
        }
        __syncthreads();

        // MMA phase
        uint32_t base = sb + GS_SPL(buf);
        uint32_t BH[2][4], BL[2][4];
#pragma unroll
        for (int p = 0; p < 2; p++) {
            uint32_t bd = base + 12288 + b_off + p * 768;
            ldsm4(BH[p], bd);
            ldsm4(BL[p], bd + 6144);
        }
#pragma unroll
        for (int mt = 0; mt < 4; mt++) {
            uint32_t AH4[4], AL4[4];
            uint32_t ad = base + a_off + mt * 768;
            ldsm4(AH4, ad);
            ldsm4(AL4, ad + 6144);
#pragma unroll
            for (int nt = 0; nt < 4; nt++) {
                const uint32_t* bh = &BH[nt >> 1][(nt & 1) * 2];
                const uint32_t* bl = &BL[nt >> 1][(nt & 1) * 2];
                mma_bf16(acc[mt][nt], AH4, bh);
                mma_bf16(acc[mt][nt], AH4, bl);
                mma_bf16(acc[mt][nt], AL4, bh);
            }
        }
    }

    // epilogue
    int g = lane >> 2, tg = lane & 3;
#pragma unroll
    for (int mt = 0; mt < 4; mt++) {
        int row = blockIdx.y * 128 + wm * 64 + mt * 16 + g;
#pragma unroll
        for (int nt = 0; nt < 4; nt++) {
            int col = blockIdx.x * 128 + wn * 32 + nt * 8 + tg * 2;
            *(float2*)(C + (size_t)row * N + col) =
                make_float2(acc[mt][nt][0], acc[mt][nt][1]);
            *(float2*)(C + (size_t)(row + 8) * N + col) =
                make_float2(acc[mt][nt][2], acc[mt][nt][3]);
        }
    }
}

// ---------------------------------------------------------------------------
// RoPE + bf16 hi/lo split of Q,K,V into head-contiguous scratch.
// ---------------------------------------------------------------------------
__device__ __forceinline__ void split_store(float x, __nv_bfloat16* ph, __nv_bfloat16* pl) {
    uint32_t hb = __float_as_uint(x) & 0xffff0000u;
    *(unsigned short*)ph = (unsigned short)(hb >> 16);
    *pl = __float2bfloat16(x - __uint_as_float(hb));
}

__global__ __launch_bounds__(256) void rope_convert() {
    int idx = blockIdx.x * 256 + threadIdx.x;
    int p = idx & 63;
    int h = (idx >> 6) & 15;
    int t = (idx >> 10) & 2047;
    int b = idx >> 21;

    float inv_freq = powf(10000.0f, -(float)p * (1.0f / 64.0f));
    float ang = (float)t * inv_freq;
    float s, c;
    sincosf(ang, &s, &c);

    size_t src = ((size_t)(b * T_SEQ + t)) * QKV_DIM + h * HD + p;
    size_t dst = ((size_t)((b * NH + h) * T_SEQ) + t) * HD + p;

    float q1 = g_qkv[src], q2 = g_qkv[src + 64];
    float qr1 = q1 * c - q2 * s, qr2 = q1 * s + q2 * c;
    split_store(qr1, &g_qh[dst], &g_ql[dst]);
    split_store(qr2, &g_qh[dst + 64], &g_ql[dst + 64]);

    float k1 = g_qkv[src + DIM], k2 = g_qkv[src + DIM + 64];
    float kr1 = k1 * c - k2 * s, kr2 = k1 * s + k2 * c;
    split_store(kr1, &g_kh[dst], &g_kl[dst]);
    split_store(kr2, &g_kh[dst + 64], &g_kl[dst + 64]);

    float v1 = g_qkv[src + 2 * DIM], v2 = g_qkv[src + 2 * DIM + 64];
    split_store(v1, &g_vh[dst], &g_vl[dst]);
    split_store(v2, &g_vh[dst + 64], &g_vl[dst + 64]);
}

// ---------------------------------------------------------------------------
// Tensor-core causal flash attention (bf16x3 split, fragment softmax).
// (unchanged from R5 passing version)
// ---------------------------------------------------------------------------
#define SST 272
#define O_QH 0
#define O_QL 17408
#define O_KH 34816
#define O_KL 52224
#define O_VH 69632
#define O_VL 87040
#define ATTN_SMEM2 104448

__global__ __launch_bounds__(128) void attn_mma() {
    extern __shared__ char sm[];
    uint32_t sb = smem_u32(sm);
    int tid = threadIdx.x, lane = tid & 31, w = tid >> 5;
    int qt = blockIdx.x, h = blockIdx.y, b = blockIdx.z;
    int q0 = qt * 64;
    size_t hb = ((size_t)(b * NH + h)) * T_SEQ;

    {
        const char* qh_g = (const char*)(g_qh + (hb + q0) * HD);
        const char* ql_g = (const char*)(g_ql + (hb + q0) * HD);
#pragma unroll
        for (int i = 0; i < 8; i++) {
            int idx = tid + i * 128;
            int r = idx >> 4, ch = idx & 15;
            int so = r * SST + ch * 16, go = r * 256 + ch * 16;
            *(uint4*)(sm + O_QH + so) = *(const uint4*)(qh_g + go);
            *(uint4*)(sm + O_QL + so) = *(const uint4*)(ql_g + go);
        }
    }

    int g = lane >> 2, tg = lane & 3;
    uint32_t q_off = (uint32_t)((w * 16 + (lane & 15)) * SST + ((lane >> 4) * 8) * 2);
    uint32_t kb_off = (uint32_t)((((lane >> 4) * 8) + (lane & 7)) * SST +
                                 (((lane >> 3) & 1) * 8) * 2);
    uint32_t v_off = (uint32_t)((lane & 15) * SST + ((lane >> 4) * 8) * 2);

    float o[16][4];
#pragma unroll
    for (int i = 0; i < 16; i++)
#pragma unroll
        for (int j = 0; j < 4; j++) o[i][j] = 0.f;

    float m0 = -1e30f, m1 = -1e30f, l0 = 0.f, l1 = 0.f;
    const float scale = 0.08838834764831845f;

    for (int kt = 0; kt <= qt; ++kt) {
        int k0 = kt * 64;
        __syncthreads();
        {
            const char* kh_g = (const char*)(g_kh + (hb + k0) * HD);
            const char* kl_g = (const char*)(g_kl + (hb + k0) * HD);
            const char* vh_g = (const char*)(g_vh + (hb + k0) * HD);
            const char* vl_g = (const char*)(g_vl + (hb + k0) * HD);
#pragma unroll
            for (int i = 0; i < 8; i++) {
                int idx = tid + i * 128;
                int r = idx >> 4, ch = idx & 15;
                int so = r * SST + ch * 16, go = r * 256 + ch * 16;
                *(uint4*)(sm + O_KH + so) = *(const uint4*)(kh_g + go);
                *(uint4*)(sm + O_KL + so) = *(const uint4*)(kl_g + go);
                *(uint4*)(sm + O_VH + so) = *(const uint4*)(vh_g + go);
                *(uint4*)(sm + O_VL + so) = *(const uint4*)(vl_g + go);
            }
        }
        __syncthreads();

        float st[8][4];
#pragma unroll
        for (int i = 0; i < 8; i++)
#pragma unroll
            for (int j = 0; j < 4; j++) st[i][j] = 0.f;

#pragma unroll
        for (int ks = 0; ks < 8; ++ks) {
            uint32_t AH4[4], AL4[4];
            ldsm4(AH4, sb + O_QH + q_off + ks * 32);
            ldsm4(AL4, sb + O_QL + q_off + ks * 32);
#pragma unroll
            for (int p = 0; p < 4; ++p) {
                uint32_t BH4[4], BL4[4];
                uint32_t ko = kb_off + p * 16 * SST + ks * 32;
                ldsm4(BH4, sb + O_KH + ko);
                ldsm4(BL4, sb + O_KL + ko);
                mma_bf16(st[2 * p], AH4, BH4);
                mma_bf16(st[2 * p], AH4, BL4);
                mma_bf16(st[2 * p], AL4, BH4);
                mma_bf16(st[2 * p + 1], AH4, BH4 + 2);
                mma_bf16(st[2 * p + 1], AH4, BL4 + 2);
                mma_bf16(st[2 * p + 1], AL4, BH4 + 2);
            }
        }

        int rowg = q0 + w * 16 + g;
        bool diag = (kt == qt);
        float mx0 = -1e30f, mx1 = -1e30f;
#pragma unroll
        for (int nt = 0; nt < 8; ++nt) {
            int c0 = k0 + nt * 8 + 2 * tg;
            st[nt][0] *= scale; st[nt][1] *= scale;
            st[nt][2] *= scale; st[nt][3] *= scale;
            if (diag) {
                if (c0 > rowg)         st[nt][0] = -1e30f;
                if (c0 + 1 > rowg)     st[nt][1] = -1e30f;
                if (c0 > rowg + 8)     st[nt][2] = -1e30f;
                if (c0 + 1 > rowg + 8) st[nt][3] = -1e30f;
            }
            mx0 = fmaxf(mx0, fmaxf(st[nt][0], st[nt][1]));
            mx1 = fmaxf(mx1, fmaxf(st[nt][2], st[nt][3]));
        }
        mx0 = fmaxf(mx0, __shfl_xor_sync(0xffffffffu, mx0, 1));
        mx0 = fmaxf(mx0, __shfl_xor_sync(0xffffffffu, mx0, 2));
        mx1 = fmaxf(mx1, __shfl_xor_sync(0xffffffffu, mx1, 1));
        mx1 = fmaxf(mx1, __shfl_xor_sync(0xffffffffu, mx1, 2));

        float mn0 = fmaxf(m0, mx0), mn1 = fmaxf(m1, mx1);
        float al0 = __expf(m0 - mn0), al1 = __expf(m1 - mn1);
        float s0 = 0.f, s1 = 0.f;
#pragma unroll
        for (int nt = 0; nt < 8; ++nt) {
            st[nt][0] = __expf(st[nt][0] - mn0);
            st[nt][1] = __expf(st[nt][1] - mn0);
            st[nt][2] = __expf(st[nt][2] - mn1);
            st[nt][3] = __expf(st[nt][3] - mn1);
            s0 += st[nt][0] + st[nt][1];
            s1 += st[nt][2] + st[nt][3];
        }
        s0 += __shfl_xor_sync(0xffffffffu, s0, 1);
        s0 += __shfl_xor_sync(0xffffffffu, s0, 2);
        s1 += __shfl_xor_sync(0xffffffffu, s1, 1);
        s1 += __shfl_xor_sync(0xffffffffu, s1, 2);
        l0 = l0 * al0 + s0;
        l1 = l1 * al1 + s1;
        m0 = mn0; m1 = mn1;

#pragma unroll
        for (int i = 0; i < 16; i++) {
            o[i][0] *= al0; o[i][1] *= al0;
            o[i][2] *= al1; o[i][3] *= al1;
        }

#pragma unroll
        for (int ks = 0; ks < 4; ++ks) {
            float e0 = st[2 * ks][0], e1 = st[2 * ks][1];
            float e2 = st[2 * ks][2], e3 = st[2 * ks][3];
            float f0 = st[2 * ks + 1][0], f1 = st[2 * ks + 1][1];
            float f2 = st[2 * ks + 1][2], f3 = st[2 * ks + 1][3];
            uint32_t PH[4], PL[4];
            PH[0] = prmt_hi(e0, e1); PH[1] = prmt_hi(e2, e3);
            PH[2] = prmt_hi(f0, f1); PH[3] = prmt_hi(f2, f3);
            PL[0] = cvt_bf2(e0 - trunc_bf(e0), e1 - trunc_bf(e1));
            PL[1] = cvt_bf2(e2 - trunc_bf(e2), e3 - trunc_bf(e3));
            PL[2] = cvt_bf2(f0 - trunc_bf(f0), f1 - trunc_bf(f1));
            PL[3] = cvt_bf2(f2 - trunc_bf(f2), f3 - trunc_bf(f3));
#pragma unroll
            for (int np = 0; np < 8; ++np) {
                uint32_t VH4[4], VL4[4];
                uint32_t vo = v_off + ks * 16 * SST + np * 32;
                ldsm4t(VH4, sb + O_VH + vo);
                ldsm4t(VL4, sb + O_VL + vo);
                mma_bf16(o[2 * np], PH, VH4);
                mma_bf16(o[2 * np], PL, VH4);
                mma_bf16(o[2 * np], PH, VL4);
                mma_bf16(o[2 * np + 1], PH, VH4 + 2);
                mma_bf16(o[2 * np + 1], PL, VH4 + 2);
                mma_bf16(o[2 * np + 1], PH, VL4 + 2);
            }
        }
    }

    float inv0 = 1.f / l0, inv1 = 1.f / l1;
    int r0 = q0 + w * 16 + g;
    float* orow0 = g_att + ((size_t)(b * T_SEQ) + r0) * DIM + h * HD;
    float* orow1 = orow0 + (size_t)8 * DIM;
#pragma unroll
    for (int np = 0; np < 16; ++np) {
        int col = np * 8 + 2 * tg;
        *(float2*)(orow0 + col) = make_float2(o[np][0] * inv0, o[np][1] * inv0);
        *(float2*)(orow1 + col) = make_float2(o[np][2] * inv1, o[np][3] * inv1);
    }
}

// ---------------------------------------------------------------------------
extern "C" void kernel_launch(void* const* d_in, const int* in_sizes, int n_in,
                              void* d_out, int out_size) {
    const float* x     = (const float*)d_in[0];  // [2,2048,2048]
    const float* w_qkv = (const float*)d_in[1];  // [6144,2048]
    const float* w_out = (const float*)d_in[2];  // [2048,2048]
    float* out = (float*)d_out;                  // [2,2048,2048]

    float* qkv_ptr = nullptr;
    float* att_ptr = nullptr;
    cudaGetSymbolAddress((void**)&qkv_ptr, g_qkv);
    cudaGetSymbolAddress((void**)&att_ptr, g_att);
    cudaFuncSetAttribute(gemm_bf16x3, cudaFuncAttributeMaxDynamicSharedMemorySize, GEMM_SMEM);
    cudaFuncSetAttribute(attn_mma, cudaFuncAttributeMaxDynamicSharedMemorySize, ATTN_SMEM2);

    // 1) QKV projection (tensor cores, bf16x3, cp.async pipeline)
    gemm_bf16x3<<<dim3(QKV_DIM / 128, 4096 / 128), 256, GEMM_SMEM>>>(x, w_qkv, qkv_ptr, QKV_DIM, DIM);
    // 2) RoPE + bf16 hi/lo split
    rope_convert<<<(2 * T_SEQ * NH * 64) / 256, 256>>>();
    // 3) causal attention (tensor cores)
    attn_mma<<<dim3(T_SEQ / 64, NH, 2), 128, ATTN_SMEM2>>>();
    // 4) output projection
    gemm_bf16x3<<<dim3(DIM / 128, 4096 / 128), 256, GEMM_SMEM>>>(att_ptr, w_out, out, DIM, DIM);
}